// round 16
// baseline (speedup 1.0000x reference)
#include <cuda_runtime.h>
#include <cuda_bf16.h>
#include <cuda_fp16.h>
#include <cstdint>

#define HOPS 8
#define FDIM 128
#define HID  256
#define NCLS 64
#define NMAX 100096

typedef unsigned long long ull;

// ---------------- scratch (device globals; no runtime alloc) ----------------
__device__ float g_sx[(size_t)NMAX * HOPS];
__device__ float g_w [(size_t)NMAX * HOPS];
__device__ __half g_W1T_h[(size_t)HID * 1024];   // [c][k]
__device__ __half g_W2T_h[(size_t)HID * HID];
__device__ __half g_Wo1T_h[(size_t)HID * FDIM];  // [c=256][k=128]
__device__ __half g_Wo2T_h[(size_t)NCLS * HID];  // [c=64][k=256]

// ---------------- helpers ----------------
__device__ __forceinline__ uint32_t smem_u32(const void* p) {
    uint32_t a;
    asm("{ .reg .u64 t; cvta.to.shared.u64 t, %1; cvt.u32.u64 %0, t; }" : "=r"(a) : "l"(p));
    return a;
}
__device__ __forceinline__ void ldsm4(uint32_t* r, uint32_t addr) {
    asm volatile("ldmatrix.sync.aligned.m8n8.x4.shared.b16 {%0,%1,%2,%3}, [%4];"
        : "=r"(r[0]), "=r"(r[1]), "=r"(r[2]), "=r"(r[3]) : "r"(addr));
}
__device__ __forceinline__ void mma16816h(float* c, const uint32_t* a, const uint32_t* b) {
    asm volatile("mma.sync.aligned.m16n8k16.row.col.f32.f16.f16.f32 "
        "{%0,%1,%2,%3}, {%4,%5,%6,%7}, {%8,%9}, {%0,%1,%2,%3};"
        : "+f"(c[0]), "+f"(c[1]), "+f"(c[2]), "+f"(c[3])
        : "r"(a[0]), "r"(a[1]), "r"(a[2]), "r"(a[3]), "r"(b[0]), "r"(b[1]));
}
#define CP_ASYNC16(dst, src) \
    asm volatile("cp.async.cg.shared.global [%0], [%1], 16;" :: "r"(dst), "l"(src))
#define CP_COMMIT() asm volatile("cp.async.commit_group;" ::: "memory")
#define CP_WAIT0()  asm volatile("cp.async.wait_group 0;" ::: "memory")

__device__ __forceinline__ float prelu_f(float v, float a) { return v >= 0.f ? v : a * v; }

union Hf8 { uint4 q; __half e[8]; };

__device__ __forceinline__ uint32_t pack_half2(float x0, float x1) {
    __half2 h = __floats2half2_rn(x0, x1);
    return *(uint32_t*)&h;
}

// ---------------------------------------------------------------------------
// k0: transpose all four weight matrices to fp16 [c][k].
// ---------------------------------------------------------------------------
__global__ void k0_convert(const float* __restrict__ W1, const float* __restrict__ W2,
                           const float* __restrict__ Wo1, const float* __restrict__ Wo2)
{
    int idx = blockIdx.x * 1024 + threadIdx.x;
    if (idx < 262144) {                       // W1 [1024][256]
        int k = idx >> 8, c = idx & 255;
        g_W1T_h[(size_t)c * 1024 + k] = __float2half_rn(W1[idx]);
        return;
    }
    if (idx < 327680) {                       // W2 [256][256]
        int i = idx - 262144, k = i >> 8, c = i & 255;
        g_W2T_h[(size_t)c * 256 + k] = __float2half_rn(W2[i]);
        return;
    }
    if (idx < 360448) {                       // Wo1 [128][256]
        int i = idx - 327680, k = i >> 8, c = i & 255;
        g_Wo1T_h[(size_t)c * 128 + k] = __float2half_rn(Wo1[i]);
        return;
    }
    if (idx < 376832) {                       // Wo2 [256][64]
        int i = idx - 360448, k = i >> 6, c = i & 63;
        g_Wo2T_h[(size_t)c * 256 + k] = __float2half_rn(Wo2[i]);
    }
}

// ---------------------------------------------------------------------------
// k12: BM=64, 256 threads, 2 CTAs/SM.  (R12 reference design, all fp16.)
// ---------------------------------------------------------------------------
#define STG    46080
#define S_AH   0
#define S_BH   9216
#define HREG   0
#define B2H    34816
#define EX_WX   108544
#define EX_B1   109056
#define EX_B2   110080
#define EX_WR   111104
#define EX_SRED 112128
#define K12_SMEM 113152

__global__ __launch_bounds__(256, 2) void k12(
    const float* __restrict__ feats, const float* __restrict__ wx,
    const float* __restrict__ b1, const float* __restrict__ a_jk_p,
    const float* __restrict__ b2, const float* __restrict__ a_main_p,
    const float* __restrict__ w_ref, const float* __restrict__ b_att_p, int N)
{
    extern __shared__ char smraw[];
    const uint32_t sb = smem_u32(smraw);
    const int tid = threadIdx.x, wid = tid >> 5, lane = tid & 31;
    const int n0 = blockIdx.x * 64;
    const int wm = wid & 1, wn = wid >> 1;          // 2M x 4N warps, tile 32x64
    const int g = lane >> 2, tg = lane & 3;
    const int sxrow = tid >> 2;

    float* wxs  = (float*)(smraw + EX_WX);
    float* sb1  = (float*)(smraw + EX_B1);
    float* sb2  = (float*)(smraw + EX_B2);
    float* swr  = (float*)(smraw + EX_WR);
    float* sred = (float*)(smraw + EX_SRED);
    if (tid < 128) wxs[tid] = wx[tid];
    sb1[tid] = b1[tid];
    sb2[tid] = b2[tid];
    swr[tid] = w_ref[tid];

    float acc[2][8][4];
    #pragma unroll
    for (int a = 0; a < 2; ++a)
        #pragma unroll
        for (int b = 0; b < 8; ++b)
            #pragma unroll
            for (int c = 0; c < 4; ++c) acc[a][b][c] = 0.f;

    const uint32_t aoff_c = (uint32_t)(wm * 32 + (lane & 15)) * 144
                          + (uint32_t)((lane >> 4) * 8) * 2;
    const int brow = (lane & 7) + ((lane >> 4) << 3);
    const int bko  = ((lane >> 3) & 1) * 8;
    const uint32_t boff_c = (uint32_t)(wn * 64 + brow) * 144 + (uint32_t)bko * 2;

    // ---------------- Phase 1: 16 K-chunks of 64, double-buffered ----------------
    float4 areg[4];
    {
        #pragma unroll
        for (int i = 0; i < 4; ++i) {
            int idx = i * 256 + tid;
            int r = idx >> 4, cq = (idx & 15) << 2;
            int n = n0 + r; if (n > N - 1) n = N - 1;
            areg[i] = *(const float4*)(feats + (size_t)n * FDIM + cq);
        }
        #pragma unroll
        for (int i = 0; i < 8; ++i) {
            int idx = i * 256 + tid;
            int r = idx >> 3, c8 = (idx & 7) << 3;
            CP_ASYNC16(sb + S_BH + r * 144 + c8 * 2, g_W1T_h + (size_t)r * 1024 + c8);
        }
        CP_COMMIT();
        #pragma unroll
        for (int i = 0; i < 4; ++i) {
            int idx = i * 256 + tid;
            int r = idx >> 4, cq = (idx & 15) << 2;
            ull u = (ull)pack_half2(areg[i].x, areg[i].y)
                  | ((ull)pack_half2(areg[i].z, areg[i].w) << 32);
            *(ull*)(smraw + S_AH + r * 144 + cq * 2) = u;
        }
    }

    float sx0 = 0.f, sx1 = 0.f;

    for (int chunk = 0; chunk < 16; ++chunk) {
        const uint32_t sbase = (uint32_t)(chunk & 1) * STG;
        const int hop = chunk >> 1, f0 = (chunk & 1) << 6;

        CP_WAIT0();
        __syncthreads();

        if (chunk < 15) {
            const int cn = chunk + 1;
            const uint32_t nbase = (uint32_t)(cn & 1) * STG;
            const int c0n = cn << 6;
            #pragma unroll
            for (int i = 0; i < 8; ++i) {
                int idx = i * 256 + tid;
                int r = idx >> 3, c8 = (idx & 7) << 3;
                CP_ASYNC16(sb + nbase + S_BH + r * 144 + c8 * 2,
                           g_W1T_h + (size_t)r * 1024 + c0n + c8);
            }
            CP_COMMIT();
            const int hop_n = cn >> 1, f0_n = (cn & 1) << 6;
            const float* fbn = feats + (size_t)hop_n * N * FDIM + f0_n;
            #pragma unroll
            for (int i = 0; i < 4; ++i) {
                int idx = i * 256 + tid;
                int r = idx >> 4, cq = (idx & 15) << 2;
                int n = n0 + r; if (n > N - 1) n = N - 1;
                areg[i] = *(const float4*)(fbn + (size_t)n * FDIM + cq);
            }
        }

        {   // fused s_x: 4 threads/row, 16 cols each
            const char* bh = smraw + sbase + S_AH + sxrow * 144 + tg * 32;
            #pragma unroll
            for (int q = 0; q < 2; ++q) {
                Hf8 qh;
                qh.q = *(const uint4*)(bh + q * 16);
                const float* wp = wxs + f0 + tg * 16 + q * 8;
                sx0 += __half2float(qh.e[0]) * wp[0] + __half2float(qh.e[2]) * wp[2]
                     + __half2float(qh.e[4]) * wp[4] + __half2float(qh.e[6]) * wp[6];
                sx1 += __half2float(qh.e[1]) * wp[1] + __half2float(qh.e[3]) * wp[3]
                     + __half2float(qh.e[5]) * wp[5] + __half2float(qh.e[7]) * wp[7];
            }
        }

        const uint32_t aH = sb + sbase + S_AH + aoff_c;
        const uint32_t bH = sb + sbase + S_BH + boff_c;
        #pragma unroll
        for (int ks = 0; ks < 4; ++ks) {
            uint32_t ah[2][4];
            ldsm4(ah[0], aH + ks * 32);
            ldsm4(ah[1], aH + 16 * 144 + ks * 32);
            #pragma unroll
            for (int ntp = 0; ntp < 4; ++ntp) {
                uint32_t bhf[4];
                ldsm4(bhf, bH + ntp * 16 * 144 + ks * 32);
                #pragma unroll
                for (int mt = 0; mt < 2; ++mt) {
                    mma16816h(acc[mt][ntp * 2],     ah[mt], bhf);
                    mma16816h(acc[mt][ntp * 2 + 1], ah[mt], bhf + 2);
                }
            }
        }

        if (chunk < 15) {
            const uint32_t nbase = (uint32_t)((chunk + 1) & 1) * STG;
            #pragma unroll
            for (int i = 0; i < 4; ++i) {
                int idx = i * 256 + tid;
                int r = idx >> 4, cq = (idx & 15) << 2;
                ull u = (ull)pack_half2(areg[i].x, areg[i].y)
                      | ((ull)pack_half2(areg[i].z, areg[i].w) << 32);
                *(ull*)(smraw + nbase + S_AH + r * 144 + cq * 2) = u;
            }
        }

        if (chunk & 1) {
            float s = sx0 + sx1;
            s += __shfl_xor_sync(0xffffffffu, s, 1);
            s += __shfl_xor_sync(0xffffffffu, s, 2);
            if (tg == 0 && n0 + sxrow < N)
                g_sx[(size_t)(n0 + sxrow) * HOPS + hop] = s;
            sx0 = sx1 = 0.f;
        }
    }
    __syncthreads();

    // kick phase-2 W2 chunk0 (into B2 buf0; overlaps epilogue 1)
    #pragma unroll
    for (int i = 0; i < 8; ++i) {
        int idx = i * 256 + tid;
        int r = idx >> 3, c8 = (idx & 7) << 3;
        CP_ASYNC16(sb + B2H + r * 144 + c8 * 2, g_W2T_h + (size_t)r * 256 + c8);
    }
    CP_COMMIT();

    // ---------------- epilogue 1: bias + prelu -> H fp16 tile in smem ----------------
    {
        const float a_jk = *a_jk_p;
        __half* hh = (__half*)(smraw + HREG);
        #pragma unroll
        for (int mt = 0; mt < 2; ++mt) {
            const int r = wm * 32 + mt * 16 + g;
            #pragma unroll
            for (int nt = 0; nt < 8; ++nt) {
                const int c = wn * 64 + nt * 8 + tg * 2;
                const float b0v = sb1[c], b1v = sb1[c + 1];
                float x0 = prelu_f(acc[mt][nt][0] + b0v, a_jk);
                float x1 = prelu_f(acc[mt][nt][1] + b1v, a_jk);
                float x2 = prelu_f(acc[mt][nt][2] + b0v, a_jk);
                float x3 = prelu_f(acc[mt][nt][3] + b1v, a_jk);
                *(uint32_t*)&hh[(size_t)r * 264 + c]       = pack_half2(x0, x1);
                *(uint32_t*)&hh[(size_t)(r + 8) * 264 + c] = pack_half2(x2, x3);
            }
        }
    }

    #pragma unroll
    for (int a = 0; a < 2; ++a)
        #pragma unroll
        for (int b = 0; b < 8; ++b)
            #pragma unroll
            for (int c = 0; c < 4; ++c) acc[a][b][c] = 0.f;

    // ---------------- Phase 2: jk = H @ W2, 4 chunks of 64, double-buffered ----------------
    const uint32_t a2H = sb + HREG + (uint32_t)(wm * 32 + (lane & 15)) * 528
                       + (uint32_t)((lane >> 4) * 8) * 2;

    for (int c2 = 0; c2 < 4; ++c2) {
        CP_WAIT0();
        __syncthreads();
        if (c2 < 3) {
            const int cn = c2 + 1;
            const uint32_t nb = sb + B2H + (uint32_t)(cn & 1) * 36864;
            #pragma unroll
            for (int i = 0; i < 8; ++i) {
                int idx = i * 256 + tid;
                int r = idx >> 3, c8 = (idx & 7) << 3;
                CP_ASYNC16(nb + r * 144 + c8 * 2,
                           g_W2T_h + (size_t)r * 256 + cn * 64 + c8);
            }
            CP_COMMIT();
        }
        const uint32_t b2f = sb + B2H + (uint32_t)(c2 & 1) * 36864 + boff_c;

        #pragma unroll
        for (int ks = 0; ks < 4; ++ks) {
            const uint32_t ko = (uint32_t)(c2 * 64 + ks * 16) * 2;
            uint32_t ah[2][4];
            ldsm4(ah[0], a2H + ko);
            ldsm4(ah[1], a2H + 16 * 528 + ko);
            #pragma unroll
            for (int ntp = 0; ntp < 4; ++ntp) {
                uint32_t bhf[4];
                ldsm4(bhf, b2f + ntp * 16 * 144 + ks * 32);
                #pragma unroll
                for (int mt = 0; mt < 2; ++mt) {
                    mma16816h(acc[mt][ntp * 2],     ah[mt], bhf);
                    mma16816h(acc[mt][ntp * 2 + 1], ah[mt], bhf + 2);
                }
            }
        }
    }

    // ---------------- epilogue 2: prelu -> dot(w_ref) -> softmax(sigmoid) ----------------
    const float a_main = *a_main_p;
    float part[2][2] = {{0.f, 0.f}, {0.f, 0.f}};
    #pragma unroll
    for (int mt = 0; mt < 2; ++mt) {
        #pragma unroll
        for (int nt = 0; nt < 8; ++nt) {
            const int c = wn * 64 + nt * 8 + tg * 2;
            const float w0 = swr[c], w1 = swr[c + 1];
            const float bb0 = sb2[c], bb1 = sb2[c + 1];
            part[mt][0] += prelu_f(acc[mt][nt][0] + bb0, a_main) * w0
                         + prelu_f(acc[mt][nt][1] + bb1, a_main) * w1;
            part[mt][1] += prelu_f(acc[mt][nt][2] + bb0, a_main) * w0
                         + prelu_f(acc[mt][nt][3] + bb1, a_main) * w1;
        }
    }
    #pragma unroll
    for (int mt = 0; mt < 2; ++mt)
        #pragma unroll
        for (int h = 0; h < 2; ++h) {
            part[mt][h] += __shfl_xor_sync(0xffffffffu, part[mt][h], 1);
            part[mt][h] += __shfl_xor_sync(0xffffffffu, part[mt][h], 2);
        }
    __syncthreads();
    if (tg == 0) {
        #pragma unroll
        for (int mt = 0; mt < 2; ++mt) {
            const int r = wm * 32 + mt * 16 + g;
            sred[r * 4 + wn]       = part[mt][0];
            sred[(r + 8) * 4 + wn] = part[mt][1];
        }
    }
    __syncthreads();

    if (tid < 64) {
        const int n = n0 + tid;
        if (n < N) {
            const float sref = sred[tid * 4] + sred[tid * 4 + 1]
                             + sred[tid * 4 + 2] + sred[tid * 4 + 3] + *b_att_p;
            const float* sxp = g_sx + (size_t)n * HOPS;
            float s[HOPS];
            float m = -1e30f;
            #pragma unroll
            for (int h = 0; h < HOPS; ++h) {
                float z = sxp[h] + sref;
                s[h] = 1.f / (1.f + expf(-z));
                m = fmaxf(m, s[h]);
            }
            float sum = 0.f;
            #pragma unroll
            for (int h = 0; h < HOPS; ++h) { s[h] = expf(s[h] - m); sum += s[h]; }
            const float inv = 1.f / sum;
            float* d = g_w + (size_t)n * HOPS;
            *(float4*)(d + 0) = make_float4(s[0] * inv, s[1] * inv, s[2] * inv, s[3] * inv);
            *(float4*)(d + 4) = make_float4(s[4] * inv, s[5] * inv, s[6] * inv, s[7] * inv);
        }
    }
}

// ---------------------------------------------------------------------------
// k3: FUSED agg (fp32 feats -> fp16 smem, no global round trip) -> FFN1 -> FFN2.
// 256 thr, BM=64, 2 CTAs/SM (92KB): one CTA's DRAM-bound agg overlaps the
// co-resident CTA's tensor-bound FFN.
// ---------------------------------------------------------------------------
#define K3_AG 0
#define K3_T  17408
#define K3_BB 51200
#define K3_SMEM 92160

__global__ __launch_bounds__(256, 2) void k3_fused(
    const float* __restrict__ feats, const float* __restrict__ bo1,
    const float* __restrict__ a_out_p, const float* __restrict__ bo2,
    float* __restrict__ out, int N)
{
    extern __shared__ char smraw[];
    const uint32_t sb = smem_u32(smraw);
    const int tid = threadIdx.x, wid = tid >> 5, lane = tid & 31;
    const int n0 = blockIdx.x * 64;
    const int g = lane >> 2, tg = lane & 3;
    const int wm = wid & 1, wn = wid >> 1;   // 2M x 4N

    // ---- load hop weights (overlay in K3_T region; consumed before t stores) ----
    float* swv = (float*)(smraw + K3_T);
    {
        int r = tid >> 2, h4 = (tid & 3) << 1;
        int n = n0 + r; if (n > N - 1) n = N - 1;
        *(float2*)&swv[r * 8 + h4] = *(const float2*)(g_w + (size_t)n * HOPS + h4);
    }

    // ---- kick FFN1 chunk0 cp.async (in flight during aggregation) ----
    #pragma unroll
    for (int i = 0; i < 4; ++i) {
        int idx = i * 256 + tid;
        int r = idx >> 2, c8 = (idx & 3) << 3;
        CP_ASYNC16(sb + K3_BB + r * 80 + c8 * 2, g_Wo1T_h + (size_t)r * 128 + c8);
    }
    CP_COMMIT();
    __syncthreads();   // swv visible

    // ---- aggregation: fp32 feats -> fp16 agg tile in smem (pitch 272B) ----
    {
        __half* ag = (__half*)(smraw + K3_AG);
        #pragma unroll
        for (int i = 0; i < 8; ++i) {
            int idx = i * 256 + tid;
            int r = idx >> 5, f = (idx & 31) << 2;
            int n = n0 + r; if (n > N - 1) n = N - 1;
            const float* wp = swv + r * 8;
            float ax = 0.f, ay = 0.f, az = 0.f, aw = 0.f;
            #pragma unroll
            for (int hop = 0; hop < HOPS; ++hop) {
                const float4 v = *(const float4*)(feats + ((size_t)hop * N + n) * FDIM + f);
                const float w = wp[hop];
                ax += w * v.x; ay += w * v.y; az += w * v.z; aw += w * v.w;
            }
            *(ull*)&ag[(size_t)r * 136 + f] =
                (ull)pack_half2(ax, ay) | ((ull)pack_half2(az, aw) << 32);
        }
    }

    const int brow = (lane & 7) + ((lane >> 4) << 3);
    const int bko  = ((lane >> 3) & 1) * 8;

    // ---- FFN1: t = prelu(agg[64x128] @ Wo1 + bo1), 4 chunks of k=32 ----
    float acc1[2][8][4];
    #pragma unroll
    for (int a = 0; a < 2; ++a)
        #pragma unroll
        for (int b = 0; b < 8; ++b)
            #pragma unroll
            for (int c = 0; c < 4; ++c) acc1[a][b][c] = 0.f;

    {
        const uint32_t aoff = sb + K3_AG + (uint32_t)(wm * 32 + (lane & 15)) * 272
                            + (uint32_t)((lane >> 4) * 8) * 2;
        const uint32_t bfrag = (uint32_t)(wn * 64 + brow) * 80 + (uint32_t)bko * 2;

        for (int c = 0; c < 4; ++c) {
            CP_WAIT0();
            __syncthreads();   // agg stores (c=0) + chunk data visible
            if (c < 3) {
                const int cn = c + 1;
                const uint32_t nb = sb + K3_BB + (uint32_t)(cn & 1) * 20480;
                #pragma unroll
                for (int i = 0; i < 4; ++i) {
                    int idx = i * 256 + tid;
                    int r = idx >> 2, c8 = (idx & 3) << 3;
                    CP_ASYNC16(nb + r * 80 + c8 * 2,
                               g_Wo1T_h + (size_t)r * 128 + cn * 32 + c8);
                }
                CP_COMMIT();
            }
            const uint32_t bH = sb + K3_BB + (uint32_t)(c & 1) * 20480 + bfrag;
            #pragma unroll
            for (int ks = 0; ks < 2; ++ks) {
                const int kglob = c * 32 + ks * 16;
                uint32_t ah[2][4];
                ldsm4(ah[0], aoff + kglob * 2);
                ldsm4(ah[1], aoff + 16 * 272 + kglob * 2);
                #pragma unroll
                for (int ntp = 0; ntp < 4; ++ntp) {
                    uint32_t bh[4];
                    ldsm4(bh, bH + ntp * 16 * 80 + ks * 32);
                    #pragma unroll
                    for (int mt = 0; mt < 2; ++mt) {
                        mma16816h(acc1[mt][ntp * 2],     ah[mt], bh);
                        mma16816h(acc1[mt][ntp * 2 + 1], ah[mt], bh + 2);
                    }
                }
            }
        }
    }
    __syncthreads();   // all FFN1 MMAs done -> BB reusable; swv dead

    // kick FFN2 chunk0 load (overlaps t epilogue)
    #pragma unroll
    for (int i = 0; i < 2; ++i) {
        int idx = i * 256 + tid;
        int r = idx >> 3, c8 = (idx & 7) << 3;
        CP_ASYNC16(sb + K3_BB + r * 144 + c8 * 2, g_Wo2T_h + (size_t)r * 256 + c8);
    }
    CP_COMMIT();

    // ---- t epilogue -> fp16 smem tile (pitch 528B) ----
    {
        const float a_out = *a_out_p;
        __half* th = (__half*)(smraw + K3_T);
        #pragma unroll
        for (int mt = 0; mt < 2; ++mt) {
            const int r = wm * 32 + mt * 16 + g;
            #pragma unroll
            for (int nt = 0; nt < 8; ++nt) {
                const int c = wn * 64 + nt * 8 + tg * 2;
                const float b0v = __ldg(&bo1[c]), b1v = __ldg(&bo1[c + 1]);
                float x0 = prelu_f(acc1[mt][nt][0] + b0v, a_out);
                float x1 = prelu_f(acc1[mt][nt][1] + b1v, a_out);
                float x2 = prelu_f(acc1[mt][nt][2] + b0v, a_out);
                float x3 = prelu_f(acc1[mt][nt][3] + b1v, a_out);
                *(uint32_t*)&th[(size_t)r * 264 + c]       = pack_half2(x0, x1);
                *(uint32_t*)&th[(size_t)(r + 8) * 264 + c] = pack_half2(x2, x3);
            }
        }
    }

    // ---- FFN2: out = t[64x256] @ Wo2 + bo2, 4 chunks of k=64 ----
    {
        float acc2[2][2][4];
        #pragma unroll
        for (int a = 0; a < 2; ++a)
            #pragma unroll
            for (int b = 0; b < 2; ++b)
                #pragma unroll
                for (int c = 0; c < 4; ++c) acc2[a][b][c] = 0.f;

        const uint32_t aoff = sb + K3_T + (uint32_t)(wm * 32 + (lane & 15)) * 528
                            + (uint32_t)((lane >> 4) * 8) * 2;
        const uint32_t bfrag = (uint32_t)(wn * 16 + brow) * 144 + (uint32_t)bko * 2;

        for (int ch = 0; ch < 4; ++ch) {
            CP_WAIT0();
            __syncthreads();   // t stores (ch=0) + chunk data visible
            if (ch < 3) {
                const int cn = ch + 1;
                const uint32_t nb = sb + K3_BB + (uint32_t)(cn & 1) * 9216;
                #pragma unroll
                for (int i = 0; i < 2; ++i) {
                    int idx = i * 256 + tid;
                    int r = idx >> 3, c8 = (idx & 7) << 3;
                    CP_ASYNC16(nb + r * 144 + c8 * 2,
                               g_Wo2T_h + (size_t)r * 256 + cn * 64 + c8);
                }
                CP_COMMIT();
            }
            const uint32_t bH = sb + K3_BB + (uint32_t)(ch & 1) * 9216 + bfrag;
            #pragma unroll
            for (int ks = 0; ks < 4; ++ks) {
                const int kglob = ch * 64 + ks * 16;
                uint32_t ah[2][4], bh[4];
                ldsm4(ah[0], aoff + kglob * 2);
                ldsm4(ah[1], aoff + 16 * 528 + kglob * 2);
                ldsm4(bh, bH + ks * 32);
                #pragma unroll
                for (int mt = 0; mt < 2; ++mt) {
                    mma16816h(acc2[mt][0], ah[mt], bh);
                    mma16816h(acc2[mt][1], ah[mt], bh + 2);
                }
            }
        }

        #pragma unroll
        for (int mt = 0; mt < 2; ++mt) {
            const int n = n0 + wm * 32 + mt * 16 + g;
            #pragma unroll
            for (int ncl = 0; ncl < 2; ++ncl) {
                const int c = wn * 16 + ncl * 8 + tg * 2;
                const float b0v = __ldg(&bo2[c]), b1v = __ldg(&bo2[c + 1]);
                if (n < N) {
                    float2 o = make_float2(acc2[mt][ncl][0] + b0v, acc2[mt][ncl][1] + b1v);
                    *(float2*)&out[(size_t)n * NCLS + c] = o;
                }
                if (n + 8 < N) {
                    float2 o = make_float2(acc2[mt][ncl][2] + b0v, acc2[mt][ncl][3] + b1v);
                    *(float2*)&out[(size_t)(n + 8) * NCLS + c] = o;
                }
            }
        }
    }
}

// ---------------------------------------------------------------------------
extern "C" void kernel_launch(void* const* d_in, const int* in_sizes, int n_in,
                              void* d_out, int out_size)
{
    const float* feats  = (const float*)d_in[0];
    const float* W_jk1  = (const float*)d_in[1];
    const float* b_jk1  = (const float*)d_in[2];
    const float* W_jk2  = (const float*)d_in[3];
    const float* b_jk2  = (const float*)d_in[4];
    const float* a_jk   = (const float*)d_in[5];
    const float* a_main = (const float*)d_in[6];
    const float* a_out  = (const float*)d_in[7];
    const float* w_ref  = (const float*)d_in[8];
    const float* w_x    = (const float*)d_in[9];
    const float* b_att  = (const float*)d_in[10];
    const float* W_o1   = (const float*)d_in[11];
    const float* b_o1   = (const float*)d_in[12];
    const float* W_o2   = (const float*)d_in[13];
    const float* b_o2   = (const float*)d_in[14];
    float* out = (float*)d_out;

    const int N = in_sizes[0] / (HOPS * FDIM);
    const int nb64 = (N + 63) / 64;

    cudaFuncSetAttribute(k12,      cudaFuncAttributeMaxDynamicSharedMemorySize, K12_SMEM);
    cudaFuncSetAttribute(k3_fused, cudaFuncAttributeMaxDynamicSharedMemorySize, K3_SMEM);

    k0_convert<<<368, 1024>>>(W_jk1, W_jk2, W_o1, W_o2);
    k12<<<nb64, 256, K12_SMEM>>>(feats, w_x, b_jk1, a_jk, b_jk2, a_main,
                                 w_ref, b_att, N);
    k3_fused<<<nb64, 256, K3_SMEM>>>(feats, b_o1, a_out, b_o2, out, N);
}

// round 17
// speedup vs baseline: 1.0116x; 1.0116x over previous
#include <cuda_runtime.h>
#include <cuda_bf16.h>
#include <cuda_fp16.h>
#include <cstdint>

#define HOPS 8
#define FDIM 128
#define HID  256
#define NCLS 64
#define NMAX 100096

typedef unsigned long long ull;

// ---------------- scratch (device globals; no runtime alloc) ----------------
__device__ float g_sx[(size_t)NMAX * HOPS];
__device__ float g_w [(size_t)NMAX * HOPS];
__device__ __half g_feats_h[(size_t)HOPS * NMAX * FDIM];  // fp16 feats (from k12)
__device__ __half g_W1T_h[(size_t)HID * 1024];   // [c][k]
__device__ __half g_W2T_h[(size_t)HID * HID];
__device__ __half g_Wo1T_h[(size_t)HID * FDIM];  // [c=256][k=128]
__device__ __half g_Wo2T_h[(size_t)NCLS * HID];  // [c=64][k=256]

// ---------------- helpers ----------------
__device__ __forceinline__ uint32_t smem_u32(const void* p) {
    uint32_t a;
    asm("{ .reg .u64 t; cvta.to.shared.u64 t, %1; cvt.u32.u64 %0, t; }" : "=r"(a) : "l"(p));
    return a;
}
__device__ __forceinline__ void ldsm4(uint32_t* r, uint32_t addr) {
    asm volatile("ldmatrix.sync.aligned.m8n8.x4.shared.b16 {%0,%1,%2,%3}, [%4];"
        : "=r"(r[0]), "=r"(r[1]), "=r"(r[2]), "=r"(r[3]) : "r"(addr));
}
__device__ __forceinline__ void mma16816h(float* c, const uint32_t* a, const uint32_t* b) {
    asm volatile("mma.sync.aligned.m16n8k16.row.col.f32.f16.f16.f32 "
        "{%0,%1,%2,%3}, {%4,%5,%6,%7}, {%8,%9}, {%0,%1,%2,%3};"
        : "+f"(c[0]), "+f"(c[1]), "+f"(c[2]), "+f"(c[3])
        : "r"(a[0]), "r"(a[1]), "r"(a[2]), "r"(a[3]), "r"(b[0]), "r"(b[1]));
}
#define CP_ASYNC16(dst, src) \
    asm volatile("cp.async.cg.shared.global [%0], [%1], 16;" :: "r"(dst), "l"(src))
#define CP_COMMIT() asm volatile("cp.async.commit_group;" ::: "memory")
#define CP_WAIT0()  asm volatile("cp.async.wait_group 0;" ::: "memory")

__device__ __forceinline__ float prelu_f(float v, float a) { return v >= 0.f ? v : a * v; }

union Hf8 { uint4 q; __half e[8]; };

__device__ __forceinline__ uint32_t pack_half2(float x0, float x1) {
    __half2 h = __floats2half2_rn(x0, x1);
    return *(uint32_t*)&h;
}

// ---------------------------------------------------------------------------
// k0: transpose all four weight matrices to fp16 [c][k].
// ---------------------------------------------------------------------------
__global__ void k0_convert(const float* __restrict__ W1, const float* __restrict__ W2,
                           const float* __restrict__ Wo1, const float* __restrict__ Wo2)
{
    int idx = blockIdx.x * 1024 + threadIdx.x;
    if (idx < 262144) {                       // W1 [1024][256]
        int k = idx >> 8, c = idx & 255;
        g_W1T_h[(size_t)c * 1024 + k] = __float2half_rn(W1[idx]);
        return;
    }
    if (idx < 327680) {                       // W2 [256][256]
        int i = idx - 262144, k = i >> 8, c = i & 255;
        g_W2T_h[(size_t)c * 256 + k] = __float2half_rn(W2[i]);
        return;
    }
    if (idx < 360448) {                       // Wo1 [128][256]
        int i = idx - 327680, k = i >> 8, c = i & 255;
        g_Wo1T_h[(size_t)c * 128 + k] = __float2half_rn(Wo1[i]);
        return;
    }
    if (idx < 376832) {                       // Wo2 [256][64]
        int i = idx - 360448, k = i >> 6, c = i & 63;
        g_Wo2T_h[(size_t)c * 256 + k] = __float2half_rn(Wo2[i]);
    }
}

// ---------------------------------------------------------------------------
// k12: BM=64, 256 threads, 2 CTAs/SM.  Side-writes fp16 feats to g_feats_h.
// ---------------------------------------------------------------------------
#define STG    46080
#define S_AH   0
#define S_BH   9216
#define HREG   0
#define B2H    34816
#define EX_WX   108544
#define EX_B1   109056
#define EX_B2   110080
#define EX_WR   111104
#define EX_SRED 112128
#define K12_SMEM 113152

__global__ __launch_bounds__(256, 2) void k12(
    const float* __restrict__ feats, const float* __restrict__ wx,
    const float* __restrict__ b1, const float* __restrict__ a_jk_p,
    const float* __restrict__ b2, const float* __restrict__ a_main_p,
    const float* __restrict__ w_ref, const float* __restrict__ b_att_p, int N)
{
    extern __shared__ char smraw[];
    const uint32_t sb = smem_u32(smraw);
    const int tid = threadIdx.x, wid = tid >> 5, lane = tid & 31;
    const int n0 = blockIdx.x * 64;
    const int wm = wid & 1, wn = wid >> 1;          // 2M x 4N warps, tile 32x64
    const int g = lane >> 2, tg = lane & 3;
    const int sxrow = tid >> 2;

    float* wxs  = (float*)(smraw + EX_WX);
    float* sb1  = (float*)(smraw + EX_B1);
    float* sb2  = (float*)(smraw + EX_B2);
    float* swr  = (float*)(smraw + EX_WR);
    float* sred = (float*)(smraw + EX_SRED);
    if (tid < 128) wxs[tid] = wx[tid];
    sb1[tid] = b1[tid];
    sb2[tid] = b2[tid];
    swr[tid] = w_ref[tid];

    float acc[2][8][4];
    #pragma unroll
    for (int a = 0; a < 2; ++a)
        #pragma unroll
        for (int b = 0; b < 8; ++b)
            #pragma unroll
            for (int c = 0; c < 4; ++c) acc[a][b][c] = 0.f;

    const uint32_t aoff_c = (uint32_t)(wm * 32 + (lane & 15)) * 144
                          + (uint32_t)((lane >> 4) * 8) * 2;
    const int brow = (lane & 7) + ((lane >> 4) << 3);
    const int bko  = ((lane >> 3) & 1) * 8;
    const uint32_t boff_c = (uint32_t)(wn * 64 + brow) * 144 + (uint32_t)bko * 2;

    // ---------------- Phase 1: 16 K-chunks of 64, double-buffered ----------------
    float4 areg[4];
    {
        #pragma unroll
        for (int i = 0; i < 4; ++i) {
            int idx = i * 256 + tid;
            int r = idx >> 4, cq = (idx & 15) << 2;
            int n = n0 + r; if (n > N - 1) n = N - 1;
            areg[i] = *(const float4*)(feats + (size_t)n * FDIM + cq);
        }
        #pragma unroll
        for (int i = 0; i < 8; ++i) {
            int idx = i * 256 + tid;
            int r = idx >> 3, c8 = (idx & 7) << 3;
            CP_ASYNC16(sb + S_BH + r * 144 + c8 * 2, g_W1T_h + (size_t)r * 1024 + c8);
        }
        CP_COMMIT();
        #pragma unroll
        for (int i = 0; i < 4; ++i) {
            int idx = i * 256 + tid;
            int r = idx >> 4, cq = (idx & 15) << 2;
            int n = n0 + r; if (n > N - 1) n = N - 1;
            ull u = (ull)pack_half2(areg[i].x, areg[i].y)
                  | ((ull)pack_half2(areg[i].z, areg[i].w) << 32);
            *(ull*)(smraw + S_AH + r * 144 + cq * 2) = u;
            *(ull*)(g_feats_h + (size_t)n * FDIM + cq) = u;   // hop 0, f0 0
        }
    }

    float sx0 = 0.f, sx1 = 0.f;

    for (int chunk = 0; chunk < 16; ++chunk) {
        const uint32_t sbase = (uint32_t)(chunk & 1) * STG;
        const int hop = chunk >> 1, f0 = (chunk & 1) << 6;

        CP_WAIT0();
        __syncthreads();

        if (chunk < 15) {
            const int cn = chunk + 1;
            const uint32_t nbase = (uint32_t)(cn & 1) * STG;
            const int c0n = cn << 6;
            #pragma unroll
            for (int i = 0; i < 8; ++i) {
                int idx = i * 256 + tid;
                int r = idx >> 3, c8 = (idx & 7) << 3;
                CP_ASYNC16(sb + nbase + S_BH + r * 144 + c8 * 2,
                           g_W1T_h + (size_t)r * 1024 + c0n + c8);
            }
            CP_COMMIT();
            const int hop_n = cn >> 1, f0_n = (cn & 1) << 6;
            const float* fbn = feats + (size_t)hop_n * N * FDIM + f0_n;
            #pragma unroll
            for (int i = 0; i < 4; ++i) {
                int idx = i * 256 + tid;
                int r = idx >> 4, cq = (idx & 15) << 2;
                int n = n0 + r; if (n > N - 1) n = N - 1;
                areg[i] = *(const float4*)(fbn + (size_t)n * FDIM + cq);
            }
        }

        {   // fused s_x: 4 threads/row, 16 cols each
            const char* bh = smraw + sbase + S_AH + sxrow * 144 + tg * 32;
            #pragma unroll
            for (int q = 0; q < 2; ++q) {
                Hf8 qh;
                qh.q = *(const uint4*)(bh + q * 16);
                const float* wp = wxs + f0 + tg * 16 + q * 8;
                sx0 += __half2float(qh.e[0]) * wp[0] + __half2float(qh.e[2]) * wp[2]
                     + __half2float(qh.e[4]) * wp[4] + __half2float(qh.e[6]) * wp[6];
                sx1 += __half2float(qh.e[1]) * wp[1] + __half2float(qh.e[3]) * wp[3]
                     + __half2float(qh.e[5]) * wp[5] + __half2float(qh.e[7]) * wp[7];
            }
        }

        const uint32_t aH = sb + sbase + S_AH + aoff_c;
        const uint32_t bH = sb + sbase + S_BH + boff_c;
        #pragma unroll
        for (int ks = 0; ks < 4; ++ks) {
            uint32_t ah[2][4];
            ldsm4(ah[0], aH + ks * 32);
            ldsm4(ah[1], aH + 16 * 144 + ks * 32);
            #pragma unroll
            for (int ntp = 0; ntp < 4; ++ntp) {
                uint32_t bhf[4];
                ldsm4(bhf, bH + ntp * 16 * 144 + ks * 32);
                #pragma unroll
                for (int mt = 0; mt < 2; ++mt) {
                    mma16816h(acc[mt][ntp * 2],     ah[mt], bhf);
                    mma16816h(acc[mt][ntp * 2 + 1], ah[mt], bhf + 2);
                }
            }
        }

        if (chunk < 15) {
            const int cn = chunk + 1;
            const uint32_t nbase = (uint32_t)(cn & 1) * STG;
            const int hop_n = cn >> 1, f0_n = (cn & 1) << 6;
            __half* gf = g_feats_h + (size_t)hop_n * N * FDIM + f0_n;
            #pragma unroll
            for (int i = 0; i < 4; ++i) {
                int idx = i * 256 + tid;
                int r = idx >> 4, cq = (idx & 15) << 2;
                int n = n0 + r; if (n > N - 1) n = N - 1;
                ull u = (ull)pack_half2(areg[i].x, areg[i].y)
                      | ((ull)pack_half2(areg[i].z, areg[i].w) << 32);
                *(ull*)(smraw + nbase + S_AH + r * 144 + cq * 2) = u;
                *(ull*)(gf + (size_t)n * FDIM + cq) = u;
            }
        }

        if (chunk & 1) {
            float s = sx0 + sx1;
            s += __shfl_xor_sync(0xffffffffu, s, 1);
            s += __shfl_xor_sync(0xffffffffu, s, 2);
            if (tg == 0 && n0 + sxrow < N)
                g_sx[(size_t)(n0 + sxrow) * HOPS + hop] = s;
            sx0 = sx1 = 0.f;
        }
    }
    __syncthreads();

    // kick phase-2 W2 chunk0 (into B2 buf0; overlaps epilogue 1)
    #pragma unroll
    for (int i = 0; i < 8; ++i) {
        int idx = i * 256 + tid;
        int r = idx >> 3, c8 = (idx & 7) << 3;
        CP_ASYNC16(sb + B2H + r * 144 + c8 * 2, g_W2T_h + (size_t)r * 256 + c8);
    }
    CP_COMMIT();

    // ---------------- epilogue 1: bias + prelu -> H fp16 tile in smem ----------------
    {
        const float a_jk = *a_jk_p;
        __half* hh = (__half*)(smraw + HREG);
        #pragma unroll
        for (int mt = 0; mt < 2; ++mt) {
            const int r = wm * 32 + mt * 16 + g;
            #pragma unroll
            for (int nt = 0; nt < 8; ++nt) {
                const int c = wn * 64 + nt * 8 + tg * 2;
                const float b0v = sb1[c], b1v = sb1[c + 1];
                float x0 = prelu_f(acc[mt][nt][0] + b0v, a_jk);
                float x1 = prelu_f(acc[mt][nt][1] + b1v, a_jk);
                float x2 = prelu_f(acc[mt][nt][2] + b0v, a_jk);
                float x3 = prelu_f(acc[mt][nt][3] + b1v, a_jk);
                *(uint32_t*)&hh[(size_t)r * 264 + c]       = pack_half2(x0, x1);
                *(uint32_t*)&hh[(size_t)(r + 8) * 264 + c] = pack_half2(x2, x3);
            }
        }
    }

    #pragma unroll
    for (int a = 0; a < 2; ++a)
        #pragma unroll
        for (int b = 0; b < 8; ++b)
            #pragma unroll
            for (int c = 0; c < 4; ++c) acc[a][b][c] = 0.f;

    // ---------------- Phase 2: jk = H @ W2, 4 chunks of 64, double-buffered ----------------
    const uint32_t a2H = sb + HREG + (uint32_t)(wm * 32 + (lane & 15)) * 528
                       + (uint32_t)((lane >> 4) * 8) * 2;

    for (int c2 = 0; c2 < 4; ++c2) {
        CP_WAIT0();
        __syncthreads();
        if (c2 < 3) {
            const int cn = c2 + 1;
            const uint32_t nb = sb + B2H + (uint32_t)(cn & 1) * 36864;
            #pragma unroll
            for (int i = 0; i < 8; ++i) {
                int idx = i * 256 + tid;
                int r = idx >> 3, c8 = (idx & 7) << 3;
                CP_ASYNC16(nb + r * 144 + c8 * 2,
                           g_W2T_h + (size_t)r * 256 + cn * 64 + c8);
            }
            CP_COMMIT();
        }
        const uint32_t b2f = sb + B2H + (uint32_t)(c2 & 1) * 36864 + boff_c;

        #pragma unroll
        for (int ks = 0; ks < 4; ++ks) {
            const uint32_t ko = (uint32_t)(c2 * 64 + ks * 16) * 2;
            uint32_t ah[2][4];
            ldsm4(ah[0], a2H + ko);
            ldsm4(ah[1], a2H + 16 * 528 + ko);
            #pragma unroll
            for (int ntp = 0; ntp < 4; ++ntp) {
                uint32_t bhf[4];
                ldsm4(bhf, b2f + ntp * 16 * 144 + ks * 32);
                #pragma unroll
                for (int mt = 0; mt < 2; ++mt) {
                    mma16816h(acc[mt][ntp * 2],     ah[mt], bhf);
                    mma16816h(acc[mt][ntp * 2 + 1], ah[mt], bhf + 2);
                }
            }
        }
    }

    // ---------------- epilogue 2: prelu -> dot(w_ref) -> softmax(sigmoid) ----------------
    const float a_main = *a_main_p;
    float part[2][2] = {{0.f, 0.f}, {0.f, 0.f}};
    #pragma unroll
    for (int mt = 0; mt < 2; ++mt) {
        #pragma unroll
        for (int nt = 0; nt < 8; ++nt) {
            const int c = wn * 64 + nt * 8 + tg * 2;
            const float w0 = swr[c], w1 = swr[c + 1];
            const float bb0 = sb2[c], bb1 = sb2[c + 1];
            part[mt][0] += prelu_f(acc[mt][nt][0] + bb0, a_main) * w0
                         + prelu_f(acc[mt][nt][1] + bb1, a_main) * w1;
            part[mt][1] += prelu_f(acc[mt][nt][2] + bb0, a_main) * w0
                         + prelu_f(acc[mt][nt][3] + bb1, a_main) * w1;
        }
    }
    #pragma unroll
    for (int mt = 0; mt < 2; ++mt)
        #pragma unroll
        for (int h = 0; h < 2; ++h) {
            part[mt][h] += __shfl_xor_sync(0xffffffffu, part[mt][h], 1);
            part[mt][h] += __shfl_xor_sync(0xffffffffu, part[mt][h], 2);
        }
    __syncthreads();
    if (tg == 0) {
        #pragma unroll
        for (int mt = 0; mt < 2; ++mt) {
            const int r = wm * 32 + mt * 16 + g;
            sred[r * 4 + wn]       = part[mt][0];
            sred[(r + 8) * 4 + wn] = part[mt][1];
        }
    }
    __syncthreads();

    if (tid < 64) {
        const int n = n0 + tid;
        if (n < N) {
            const float sref = sred[tid * 4] + sred[tid * 4 + 1]
                             + sred[tid * 4 + 2] + sred[tid * 4 + 3] + *b_att_p;
            const float* sxp = g_sx + (size_t)n * HOPS;
            float s[HOPS];
            float m = -1e30f;
            #pragma unroll
            for (int h = 0; h < HOPS; ++h) {
                float z = sxp[h] + sref;
                s[h] = 1.f / (1.f + expf(-z));
                m = fmaxf(m, s[h]);
            }
            float sum = 0.f;
            #pragma unroll
            for (int h = 0; h < HOPS; ++h) { s[h] = expf(s[h] - m); sum += s[h]; }
            const float inv = 1.f / sum;
            float* d = g_w + (size_t)n * HOPS;
            *(float4*)(d + 0) = make_float4(s[0] * inv, s[1] * inv, s[2] * inv, s[3] * inv);
            *(float4*)(d + 4) = make_float4(s[4] * inv, s[5] * inv, s[6] * inv, s[7] * inv);
        }
    }
}

// ---------------------------------------------------------------------------
// k3: FUSED agg (fp16 feats -> fp16 smem) -> FFN1 -> FFN2.
// 256 thr, BM=64, 2 CTAs/SM (92KB).
// ---------------------------------------------------------------------------
#define K3_AG 0
#define K3_T  17408
#define K3_BB 51200
#define K3_SMEM 92160

__global__ __launch_bounds__(256, 2) void k3_fused(
    const float* __restrict__ bo1, const float* __restrict__ a_out_p,
    const float* __restrict__ bo2, float* __restrict__ out, int N)
{
    extern __shared__ char smraw[];
    const uint32_t sb = smem_u32(smraw);
    const int tid = threadIdx.x, wid = tid >> 5, lane = tid & 31;
    const int n0 = blockIdx.x * 64;
    const int g = lane >> 2, tg = lane & 3;
    const int wm = wid & 1, wn = wid >> 1;   // 2M x 4N

    // ---- load hop weights (overlay in K3_T region; consumed before t stores) ----
    float* swv = (float*)(smraw + K3_T);
    {
        int r = tid >> 2, h4 = (tid & 3) << 1;
        int n = n0 + r; if (n > N - 1) n = N - 1;
        *(float2*)&swv[r * 8 + h4] = *(const float2*)(g_w + (size_t)n * HOPS + h4);
    }

    // ---- kick FFN1 chunk0 cp.async (in flight during aggregation) ----
    #pragma unroll
    for (int i = 0; i < 4; ++i) {
        int idx = i * 256 + tid;
        int r = idx >> 2, c8 = (idx & 3) << 3;
        CP_ASYNC16(sb + K3_BB + r * 80 + c8 * 2, g_Wo1T_h + (size_t)r * 128 + c8);
    }
    CP_COMMIT();
    __syncthreads();   // swv visible

    // ---- aggregation: fp16 feats -> fp16 agg tile in smem (pitch 272B) ----
    {
        __half* ag = (__half*)(smraw + K3_AG);
        #pragma unroll
        for (int i = 0; i < 4; ++i) {
            int idx = i * 256 + tid;
            int r = idx >> 4, f = (idx & 15) << 3;
            int n = n0 + r; if (n > N - 1) n = N - 1;
            const float* wp = swv + r * 8;
            float a[8];
            #pragma unroll
            for (int j = 0; j < 8; ++j) a[j] = 0.f;
            #pragma unroll
            for (int hop = 0; hop < HOPS; ++hop) {
                Hf8 v;
                v.q = *(const uint4*)(g_feats_h + ((size_t)hop * N + n) * FDIM + f);
                const float w = wp[hop];
                #pragma unroll
                for (int j = 0; j < 8; ++j) a[j] += w * __half2float(v.e[j]);
            }
            uint4 o;
            o.x = pack_half2(a[0], a[1]);
            o.y = pack_half2(a[2], a[3]);
            o.z = pack_half2(a[4], a[5]);
            o.w = pack_half2(a[6], a[7]);
            *(uint4*)&ag[(size_t)r * 136 + f] = o;
        }
    }

    const int brow = (lane & 7) + ((lane >> 4) << 3);
    const int bko  = ((lane >> 3) & 1) * 8;

    // ---- FFN1: t = prelu(agg[64x128] @ Wo1 + bo1), 4 chunks of k=32 ----
    float acc1[2][8][4];
    #pragma unroll
    for (int a = 0; a < 2; ++a)
        #pragma unroll
        for (int b = 0; b < 8; ++b)
            #pragma unroll
            for (int c = 0; c < 4; ++c) acc1[a][b][c] = 0.f;

    {
        const uint32_t aoff = sb + K3_AG + (uint32_t)(wm * 32 + (lane & 15)) * 272
                            + (uint32_t)((lane >> 4) * 8) * 2;
        const uint32_t bfrag = (uint32_t)(wn * 64 + brow) * 80 + (uint32_t)bko * 2;

        for (int c = 0; c < 4; ++c) {
            CP_WAIT0();
            __syncthreads();   // agg stores (c=0) + chunk data visible
            if (c < 3) {
                const int cn = c + 1;
                const uint32_t nb = sb + K3_BB + (uint32_t)(cn & 1) * 20480;
                #pragma unroll
                for (int i = 0; i < 4; ++i) {
                    int idx = i * 256 + tid;
                    int r = idx >> 2, c8 = (idx & 3) << 3;
                    CP_ASYNC16(nb + r * 80 + c8 * 2,
                               g_Wo1T_h + (size_t)r * 128 + cn * 32 + c8);
                }
                CP_COMMIT();
            }
            const uint32_t bH = sb + K3_BB + (uint32_t)(c & 1) * 20480 + bfrag;
            #pragma unroll
            for (int ks = 0; ks < 2; ++ks) {
                const int kglob = c * 32 + ks * 16;
                uint32_t ah[2][4];
                ldsm4(ah[0], aoff + kglob * 2);
                ldsm4(ah[1], aoff + 16 * 272 + kglob * 2);
                #pragma unroll
                for (int ntp = 0; ntp < 4; ++ntp) {
                    uint32_t bh[4];
                    ldsm4(bh, bH + ntp * 16 * 80 + ks * 32);
                    #pragma unroll
                    for (int mt = 0; mt < 2; ++mt) {
                        mma16816h(acc1[mt][ntp * 2],     ah[mt], bh);
                        mma16816h(acc1[mt][ntp * 2 + 1], ah[mt], bh + 2);
                    }
                }
            }
        }
    }
    __syncthreads();   // all FFN1 MMAs done -> BB reusable; swv dead

    // kick FFN2 chunk0 load (overlaps t epilogue)
    #pragma unroll
    for (int i = 0; i < 2; ++i) {
        int idx = i * 256 + tid;
        int r = idx >> 3, c8 = (idx & 7) << 3;
        CP_ASYNC16(sb + K3_BB + r * 144 + c8 * 2, g_Wo2T_h + (size_t)r * 256 + c8);
    }
    CP_COMMIT();

    // ---- t epilogue -> fp16 smem tile (pitch 528B) ----
    {
        const float a_out = *a_out_p;
        __half* th = (__half*)(smraw + K3_T);
        #pragma unroll
        for (int mt = 0; mt < 2; ++mt) {
            const int r = wm * 32 + mt * 16 + g;
            #pragma unroll
            for (int nt = 0; nt < 8; ++nt) {
                const int c = wn * 64 + nt * 8 + tg * 2;
                const float b0v = __ldg(&bo1[c]), b1v = __ldg(&bo1[c + 1]);
                float x0 = prelu_f(acc1[mt][nt][0] + b0v, a_out);
                float x1 = prelu_f(acc1[mt][nt][1] + b1v, a_out);
                float x2 = prelu_f(acc1[mt][nt][2] + b0v, a_out);
                float x3 = prelu_f(acc1[mt][nt][3] + b1v, a_out);
                *(uint32_t*)&th[(size_t)r * 264 + c]       = pack_half2(x0, x1);
                *(uint32_t*)&th[(size_t)(r + 8) * 264 + c] = pack_half2(x2, x3);
            }
        }
    }

    // ---- FFN2: out = t[64x256] @ Wo2 + bo2, 4 chunks of k=64 ----
    {
        float acc2[2][2][4];
        #pragma unroll
        for (int a = 0; a < 2; ++a)
            #pragma unroll
            for (int b = 0; b < 2; ++b)
                #pragma unroll
                for (int c = 0; c < 4; ++c) acc2[a][b][c] = 0.f;

        const uint32_t aoff = sb + K3_T + (uint32_t)(wm * 32 + (lane & 15)) * 528
                            + (uint32_t)((lane >> 4) * 8) * 2;
        const uint32_t bfrag = (uint32_t)(wn * 16 + brow) * 144 + (uint32_t)bko * 2;

        for (int ch = 0; ch < 4; ++ch) {
            CP_WAIT0();
            __syncthreads();   // t stores (ch=0) + chunk data visible
            if (ch < 3) {
                const int cn = ch + 1;
                const uint32_t nb = sb + K3_BB + (uint32_t)(cn & 1) * 9216;
                #pragma unroll
                for (int i = 0; i < 2; ++i) {
                    int idx = i * 256 + tid;
                    int r = idx >> 3, c8 = (idx & 7) << 3;
                    CP_ASYNC16(nb + r * 144 + c8 * 2,
                               g_Wo2T_h + (size_t)r * 256 + cn * 64 + c8);
                }
                CP_COMMIT();
            }
            const uint32_t bH = sb + K3_BB + (uint32_t)(ch & 1) * 9216 + bfrag;
            #pragma unroll
            for (int ks = 0; ks < 4; ++ks) {
                const int kglob = ch * 64 + ks * 16;
                uint32_t ah[2][4], bh[4];
                ldsm4(ah[0], aoff + kglob * 2);
                ldsm4(ah[1], aoff + 16 * 528 + kglob * 2);
                ldsm4(bh, bH + ks * 32);
                #pragma unroll
                for (int mt = 0; mt < 2; ++mt) {
                    mma16816h(acc2[mt][0], ah[mt], bh);
                    mma16816h(acc2[mt][1], ah[mt], bh + 2);
                }
            }
        }

        #pragma unroll
        for (int mt = 0; mt < 2; ++mt) {
            const int n = n0 + wm * 32 + mt * 16 + g;
            #pragma unroll
            for (int ncl = 0; ncl < 2; ++ncl) {
                const int c = wn * 16 + ncl * 8 + tg * 2;
                const float b0v = __ldg(&bo2[c]), b1v = __ldg(&bo2[c + 1]);
                if (n < N) {
                    float2 o = make_float2(acc2[mt][ncl][0] + b0v, acc2[mt][ncl][1] + b1v);
                    *(float2*)&out[(size_t)n * NCLS + c] = o;
                }
                if (n + 8 < N) {
                    float2 o = make_float2(acc2[mt][ncl][2] + b0v, acc2[mt][ncl][3] + b1v);
                    *(float2*)&out[(size_t)(n + 8) * NCLS + c] = o;
                }
            }
        }
    }
}

// ---------------------------------------------------------------------------
extern "C" void kernel_launch(void* const* d_in, const int* in_sizes, int n_in,
                              void* d_out, int out_size)
{
    const float* feats  = (const float*)d_in[0];
    const float* W_jk1  = (const float*)d_in[1];
    const float* b_jk1  = (const float*)d_in[2];
    const float* W_jk2  = (const float*)d_in[3];
    const float* b_jk2  = (const float*)d_in[4];
    const float* a_jk   = (const float*)d_in[5];
    const float* a_main = (const float*)d_in[6];
    const float* a_out  = (const float*)d_in[7];
    const float* w_ref  = (const float*)d_in[8];
    const float* w_x    = (const float*)d_in[9];
    const float* b_att  = (const float*)d_in[10];
    const float* W_o1   = (const float*)d_in[11];
    const float* b_o1   = (const float*)d_in[12];
    const float* W_o2   = (const float*)d_in[13];
    const float* b_o2   = (const float*)d_in[14];
    float* out = (float*)d_out;

    const int N = in_sizes[0] / (HOPS * FDIM);
    const int nb64 = (N + 63) / 64;

    cudaFuncSetAttribute(k12,      cudaFuncAttributeMaxDynamicSharedMemorySize, K12_SMEM);
    cudaFuncSetAttribute(k3_fused, cudaFuncAttributeMaxDynamicSharedMemorySize, K3_SMEM);

    k0_convert<<<368, 1024>>>(W_jk1, W_jk2, W_o1, W_o2);
    k12<<<nb64, 256, K12_SMEM>>>(feats, w_x, b_jk1, a_jk, b_jk2, a_main,
                                 w_ref, b_att, N);
    k3_fused<<<nb64, 256, K3_SMEM>>>(b_o1, a_out, b_o2, out, N);
}